// round 1
// baseline (speedup 1.0000x reference)
#include <cuda_runtime.h>
#include <math.h>

// Problem dims (fixed by the reference)
#define B_   8
#define L_   2048
#define E_   1024
#define H_   8
#define P_   128
#define M_   (B_ * L_)   // 16384
#define RAD  8           // Gaussian truncation radius; exp(-32) ~ 1.3e-14

// Scratch (allocation-free rule: __device__ globals)
__device__ float g_V[(size_t)M_ * E_];
__device__ float g_U[(size_t)M_ * E_];

// ---------------------------------------------------------------------------
// SGEMM: C[M,N] = A[M,K] @ Bm[N,K]^T   (both operands K-contiguous row-major)
// BM=BN=128, BK=8, 256 threads, 8x8 per thread.
// ---------------------------------------------------------------------------
__global__ __launch_bounds__(256) void sgemm_abt(
    const float* __restrict__ A,
    const float* __restrict__ Bm,
    float* __restrict__ C,
    int M, int N, int K)
{
    const int BK = 8;
    __shared__ float As[BK][128];
    __shared__ float Bs[BK][128];

    const int tid = threadIdx.x;
    const int blockRow = blockIdx.y;
    const int blockCol = blockIdx.x;

    const float* Ab = A + (size_t)blockRow * 128 * K;
    const float* Bb = Bm + (size_t)blockCol * 128 * K;
    float* Cb = C + (size_t)blockRow * 128 * N + (size_t)blockCol * 128;

    const int loadRow = tid >> 1;        // 0..127
    const int loadCol = (tid & 1) * 4;   // 0 or 4

    const int tr = tid >> 4;             // 0..15
    const int tc = tid & 15;             // 0..15

    float acc[8][8];
#pragma unroll
    for (int i = 0; i < 8; i++)
#pragma unroll
        for (int j = 0; j < 8; j++) acc[i][j] = 0.0f;

    for (int k0 = 0; k0 < K; k0 += BK) {
        float4 a4 = *reinterpret_cast<const float4*>(Ab + (size_t)loadRow * K + k0 + loadCol);
        float4 b4 = *reinterpret_cast<const float4*>(Bb + (size_t)loadRow * K + k0 + loadCol);
        As[loadCol + 0][loadRow] = a4.x;
        As[loadCol + 1][loadRow] = a4.y;
        As[loadCol + 2][loadRow] = a4.z;
        As[loadCol + 3][loadRow] = a4.w;
        Bs[loadCol + 0][loadRow] = b4.x;
        Bs[loadCol + 1][loadRow] = b4.y;
        Bs[loadCol + 2][loadRow] = b4.z;
        Bs[loadCol + 3][loadRow] = b4.w;
        __syncthreads();

#pragma unroll
        for (int k = 0; k < BK; k++) {
            float ra[8], rb[8];
#pragma unroll
            for (int i = 0; i < 8; i++) ra[i] = As[k][tr * 8 + i];
#pragma unroll
            for (int j = 0; j < 8; j++) rb[j] = Bs[k][tc * 8 + j];
#pragma unroll
            for (int i = 0; i < 8; i++)
#pragma unroll
                for (int j = 0; j < 8; j++)
                    acc[i][j] = fmaf(ra[i], rb[j], acc[i][j]);
        }
        __syncthreads();
    }

#pragma unroll
    for (int i = 0; i < 8; i++) {
        const int row = tr * 8 + i;
        float4 o0 = make_float4(acc[i][0], acc[i][1], acc[i][2], acc[i][3]);
        float4 o1 = make_float4(acc[i][4], acc[i][5], acc[i][6], acc[i][7]);
        *reinterpret_cast<float4*>(Cb + (size_t)row * N + tc * 8) = o0;
        *reinterpret_cast<float4*>(Cb + (size_t)row * N + tc * 8 + 4) = o1;
    }
}

// ---------------------------------------------------------------------------
// Gaussian smoothing along sequence, per head.
// POSITIONS = [center,left,right,first,last,center,left,right]
// center c: C=q, L=q-1, R=q+1, F=0, La=L-1. Weights exp(-d^2/2), renormalized
// over taps that fall inside [0, L-1]  (residual mass < 1e-14, far below tol).
// One block per (b,q); 256 threads stride over the 1024 embed columns.
// ---------------------------------------------------------------------------
__global__ __launch_bounds__(256) void smooth_kernel(
    const float* __restrict__ V, float* __restrict__ U)
{
    __shared__ float wt[RAD + 1];
    if (threadIdx.x <= RAD) {
        float d = (float)threadIdx.x;
        wt[threadIdx.x] = expf(-0.5f * d * d);
    }
    __syncthreads();

    const int n = blockIdx.x;        // b*L + q
    const int b = n >> 11;           // / 2048
    const int q = n & (L_ - 1);

    for (int e = threadIdx.x; e < E_; e += blockDim.x) {
        const int h = e >> 7;
        int c;
        switch (h) {
            case 0: case 5: c = q;        break;  // center
            case 1: case 6: c = q - 1;    break;  // left
            case 2: case 7: c = q + 1;    break;  // right
            case 3:         c = 0;        break;  // first
            default:        c = L_ - 1;   break;  // last
        }
        float wsum = 0.0f, accv = 0.0f;
#pragma unroll
        for (int d = -RAD; d <= RAD; d++) {
            const int j = c + d;
            if (j >= 0 && j < L_) {
                const float w = wt[d < 0 ? -d : d];
                wsum += w;
                accv = fmaf(w, V[((size_t)b * L_ + j) * E_ + e], accv);
            }
        }
        U[(size_t)n * E_ + e] = accv / wsum;
    }
}

// ---------------------------------------------------------------------------
extern "C" void kernel_launch(void* const* d_in, const int* in_sizes, int n_in,
                              void* d_out, int out_size)
{
    (void)in_sizes; (void)n_in; (void)out_size;
    const float* x     = (const float*)d_in[0];   // [B, L, E]
    const float* W_in  = (const float*)d_in[1];   // [E, E]
    const float* W_out = (const float*)d_in[2];   // [E, E]
    float* out = (float*)d_out;                   // [B, L, E]

    float* V;
    float* U;
    cudaGetSymbolAddress((void**)&V, g_V);
    cudaGetSymbolAddress((void**)&U, g_U);

    dim3 block(256);
    dim3 gridGemm(E_ / 128, M_ / 128);   // (8, 128)

    // V = X @ W_in^T
    sgemm_abt<<<gridGemm, block>>>(x, W_in, V, M_, E_, E_);
    // U = per-head Gaussian smoothing of V along sequence
    smooth_kernel<<<M_, block>>>(V, U);
    // out = U @ W_out^T
    sgemm_abt<<<gridGemm, block>>>(U, W_out, out, M_, E_, E_);
}

// round 4
// speedup vs baseline: 2.4820x; 2.4820x over previous
#include <cuda_runtime.h>
#include <cuda_bf16.h>
#include <cstdint>

// Problem dims (fixed)
#define B_   8
#define L_   2048
#define E_   1024
#define M_   (B_ * L_)   // 16384
#define RAD  8

// ---------------------------------------------------------------------------
// Scratch (__device__ globals; allocation-free rule)
// ---------------------------------------------------------------------------
__device__ __nv_bfloat16 g_Xh[(size_t)M_ * E_];
__device__ __nv_bfloat16 g_Xl[(size_t)M_ * E_];
__device__ __nv_bfloat16 g_Wih[(size_t)E_ * E_];
__device__ __nv_bfloat16 g_Wil[(size_t)E_ * E_];
__device__ __nv_bfloat16 g_Woh[(size_t)E_ * E_];
__device__ __nv_bfloat16 g_Wol[(size_t)E_ * E_];
__device__ float         g_Vf [(size_t)M_ * E_];
__device__ __nv_bfloat16 g_Uh[(size_t)M_ * E_];
__device__ __nv_bfloat16 g_Ul[(size_t)M_ * E_];

__device__ __forceinline__ uint32_t smem_u32(const void* p) {
    uint32_t a;
    asm("{ .reg .u64 t; cvta.to.shared.u64 t, %1; cvt.u32.u64 %0, t; }" : "=r"(a) : "l"(p));
    return a;
}

// ---------------------------------------------------------------------------
// GEMM: C[M,1024] = A[M,1024] @ W[1024,1024]^T via bf16 split (3 HMMA terms).
// mma.sync m16n8k16 (plain sm_80+ PTX — sm_103a-only tcgen05 is rejected by
// this harness's ptxas target). BM=BN=128, BK=64, 256 thr, warp tile 32x64.
// smem rows of 128B with SW128 swizzle -> conflict-free ldmatrix & stores.
// ---------------------------------------------------------------------------
#define GBM 128
#define GBN 128
#define GBK 64
#define NCHUNK (E_ / GBK)   // 16

#define SMA_H 0
#define SMA_L 16384
#define SMW_H 32768
#define SMW_L 49152
#define SM_TOTAL 65536

__global__ __launch_bounds__(256, 2) void gemm_mma(
    const __nv_bfloat16* __restrict__ Ah, const __nv_bfloat16* __restrict__ Al,
    const __nv_bfloat16* __restrict__ Wh, const __nv_bfloat16* __restrict__ Wl,
    float* __restrict__ C)
{
    extern __shared__ char smem[];
    const uint32_t smem_base = smem_u32(smem);

    const int tid  = threadIdx.x;
    const int wid  = tid >> 5;
    const int lane = tid & 31;
    const int wm   = wid & 3;    // 0..3  -> M offset wm*32
    const int wn   = wid >> 2;   // 0..1  -> N offset wn*64

    const size_t mrow0 = (size_t)blockIdx.y * GBM;
    const size_t nrow0 = (size_t)blockIdx.x * GBN;

    // Per-lane ldmatrix addressing (byte offsets within a 128x64-bf16 tile,
    // rows of 128 bytes, SW128 swizzle: col ^= (row&7)*16).
    // A x4: lanes 0-15 -> rows (lane&15) @k0, lanes 16-31 -> same rows @k0+8.
    // B x4: lanes: n=(lane&7)+((lane>>4)&1)*8, kc=(lane>>3)&1.
    uint32_t aRow[2], bRow[4];
#pragma unroll
    for (int mt = 0; mt < 2; mt++)
        aRow[mt] = (uint32_t)(wm * 32 + mt * 16 + (lane & 15)) * 128;
#pragma unroll
    for (int g = 0; g < 4; g++)
        bRow[g] = (uint32_t)(wn * 64 + g * 16 + (lane & 7) + ((lane >> 4) & 1) * 8) * 128;
    const uint32_t cA = ((((lane >> 4) & 1) * 16) ^ ((lane & 7) * 16));
    const uint32_t cB = ((((lane >> 3) & 1) * 16) ^ ((lane & 7) * 16));

    float acc[2][8][4];
#pragma unroll
    for (int mt = 0; mt < 2; mt++)
#pragma unroll
        for (int nt = 0; nt < 8; nt++)
#pragma unroll
            for (int r = 0; r < 4; r++) acc[mt][nt][r] = 0.0f;

#pragma unroll 1
    for (int ch = 0; ch < NCHUNK; ch++) {
        const int kbase = ch * GBK;
        // Cooperative tile loads: 4 tiles of 128 rows x 64 bf16 (128B rows).
        // u in 0..1023: row=u>>3, seg=u&7 (8x16B per row).
#pragma unroll
        for (int rep = 0; rep < 4; rep++) {
            const int u = tid + rep * 256;
            const int row = u >> 3, seg = u & 7;
            const uint32_t so = (uint32_t)row * 128 + (uint32_t)((seg * 16) ^ ((row & 7) * 16));
            const size_t ga = (mrow0 + row) * E_ + kbase + seg * 8;
            const size_t gw = (nrow0 + row) * E_ + kbase + seg * 8;
            *(uint4*)(smem + SMA_H + so) = *(const uint4*)(Ah + ga);
            *(uint4*)(smem + SMA_L + so) = *(const uint4*)(Al + ga);
            *(uint4*)(smem + SMW_H + so) = *(const uint4*)(Wh + gw);
            *(uint4*)(smem + SMW_L + so) = *(const uint4*)(Wl + gw);
        }
        __syncthreads();

#pragma unroll
        for (int term = 0; term < 3; term++) {
            const uint32_t baseA = smem_base + (term == 2 ? SMA_L : SMA_H);
            const uint32_t baseW = smem_base + (term == 1 ? SMW_L : SMW_H);
#pragma unroll
            for (int ks = 0; ks < 4; ks++) {
                const uint32_t kb = (uint32_t)(ks * 32);   // byte offset of k0
                uint32_t a[2][4];
#pragma unroll
                for (int mt = 0; mt < 2; mt++) {
                    const uint32_t ad = baseA + aRow[mt] + (kb ^ cA);
                    asm volatile(
                        "ldmatrix.sync.aligned.m8n8.x4.shared.b16 {%0,%1,%2,%3}, [%4];"
                        : "=r"(a[mt][0]), "=r"(a[mt][1]), "=r"(a[mt][2]), "=r"(a[mt][3])
                        : "r"(ad));
                }
                uint32_t b[8][2];
#pragma unroll
                for (int g = 0; g < 4; g++) {
                    const uint32_t bd = baseW + bRow[g] + (kb ^ cB);
                    uint32_t r0, r1, r2, r3;
                    asm volatile(
                        "ldmatrix.sync.aligned.m8n8.x4.shared.b16 {%0,%1,%2,%3}, [%4];"
                        : "=r"(r0), "=r"(r1), "=r"(r2), "=r"(r3)
                        : "r"(bd));
                    b[g * 2 + 0][0] = r0; b[g * 2 + 0][1] = r1;
                    b[g * 2 + 1][0] = r2; b[g * 2 + 1][1] = r3;
                }
#pragma unroll
                for (int mt = 0; mt < 2; mt++)
#pragma unroll
                    for (int nt = 0; nt < 8; nt++) {
                        asm volatile(
                            "mma.sync.aligned.m16n8k16.row.col.f32.bf16.bf16.f32 "
                            "{%0,%1,%2,%3}, {%4,%5,%6,%7}, {%8,%9}, {%0,%1,%2,%3};"
                            : "+f"(acc[mt][nt][0]), "+f"(acc[mt][nt][1]),
                              "+f"(acc[mt][nt][2]), "+f"(acc[mt][nt][3])
                            : "r"(a[mt][0]), "r"(a[mt][1]), "r"(a[mt][2]), "r"(a[mt][3]),
                              "r"(b[nt][0]), "r"(b[nt][1]));
                    }
            }
        }
        __syncthreads();
    }

    // Epilogue: acc[mt][nt] covers rows wm*32+mt*16+{l/4, l/4+8},
    // cols wn*64+nt*8+(l%4)*2 (+1). float2 stores.
    const int qr = lane >> 2;        // 0..7
    const int qc = (lane & 3) * 2;   // 0,2,4,6
#pragma unroll
    for (int mt = 0; mt < 2; mt++) {
        const size_t r0 = mrow0 + wm * 32 + mt * 16 + qr;
#pragma unroll
        for (int nt = 0; nt < 8; nt++) {
            const size_t col = nrow0 + wn * 64 + nt * 8 + qc;
            *(float2*)(C + r0 * E_ + col)       = make_float2(acc[mt][nt][0], acc[mt][nt][1]);
            *(float2*)(C + (r0 + 8) * E_ + col) = make_float2(acc[mt][nt][2], acc[mt][nt][3]);
        }
    }
}

// ---------------------------------------------------------------------------
// fp32 -> bf16 hi/lo split conversion (float4 vectorized)
// ---------------------------------------------------------------------------
__global__ __launch_bounds__(256) void conv_split(
    const float* __restrict__ in, __nv_bfloat16* __restrict__ hi,
    __nv_bfloat16* __restrict__ lo, int n4)
{
    int idx = blockIdx.x * 256 + threadIdx.x;
    if (idx >= n4) return;
    float4 v = ((const float4*)in)[idx];
    __nv_bfloat16 h0 = __float2bfloat16(v.x), h1 = __float2bfloat16(v.y);
    __nv_bfloat16 h2 = __float2bfloat16(v.z), h3 = __float2bfloat16(v.w);
    __nv_bfloat16 l0 = __float2bfloat16(v.x - __bfloat162float(h0));
    __nv_bfloat16 l1 = __float2bfloat16(v.y - __bfloat162float(h1));
    __nv_bfloat16 l2 = __float2bfloat16(v.z - __bfloat162float(h2));
    __nv_bfloat16 l3 = __float2bfloat16(v.w - __bfloat162float(h3));
    __nv_bfloat162 hp0; hp0.x = h0; hp0.y = h1;
    __nv_bfloat162 hp1; hp1.x = h2; hp1.y = h3;
    __nv_bfloat162 lp0; lp0.x = l0; lp0.y = l1;
    __nv_bfloat162 lp1; lp1.x = l2; lp1.y = l3;
    uint2 hw, lw;
    hw.x = *(uint32_t*)&hp0; hw.y = *(uint32_t*)&hp1;
    lw.x = *(uint32_t*)&lp0; lw.y = *(uint32_t*)&lp1;
    ((uint2*)hi)[idx] = hw;
    ((uint2*)lo)[idx] = lw;
}

// ---------------------------------------------------------------------------
// Gaussian smoothing along sequence (17 taps, float4 over embed dim),
// reading fp32 V, writing bf16 hi/lo U for GEMM2.
// ---------------------------------------------------------------------------
__global__ __launch_bounds__(256) void smooth_kernel(
    const float* __restrict__ V, __nv_bfloat16* __restrict__ Uh,
    __nv_bfloat16* __restrict__ Ul)
{
    const float wt[RAD + 1] = {1.0f, 0.60653066f, 0.13533528f, 0.011108997f,
                               3.3546263e-4f, 3.7266532e-6f, 1.5229979e-8f,
                               2.2897348e-11f, 1.2664166e-14f};
    const int n = blockIdx.x;        // b*L + q
    const int b = n >> 11;
    const int q = n & (L_ - 1);
    const int e = threadIdx.x * 4;   // 4 consecutive embed cols
    const int h = e >> 7;            // head

    int c;
    switch (h) {
        case 0: case 5: c = q;      break;   // center
        case 1: case 6: c = q - 1;  break;   // left
        case 2: case 7: c = q + 1;  break;   // right
        case 3:         c = 0;      break;   // first
        default:        c = L_ - 1; break;   // last
    }

    float ax = 0.f, ay = 0.f, az = 0.f, aw = 0.f, wsum = 0.f;
#pragma unroll
    for (int d = -RAD; d <= RAD; d++) {
        const int j = c + d;
        if (j >= 0 && j < L_) {
            const float w = wt[d < 0 ? -d : d];
            wsum += w;
            const float4 v = *(const float4*)(V + ((size_t)b * L_ + j) * E_ + e);
            ax = fmaf(w, v.x, ax); ay = fmaf(w, v.y, ay);
            az = fmaf(w, v.z, az); aw = fmaf(w, v.w, aw);
        }
    }
    const float inv = 1.0f / wsum;
    ax *= inv; ay *= inv; az *= inv; aw *= inv;

    __nv_bfloat16 h0 = __float2bfloat16(ax), h1 = __float2bfloat16(ay);
    __nv_bfloat16 h2 = __float2bfloat16(az), h3 = __float2bfloat16(aw);
    __nv_bfloat16 l0 = __float2bfloat16(ax - __bfloat162float(h0));
    __nv_bfloat16 l1 = __float2bfloat16(ay - __bfloat162float(h1));
    __nv_bfloat16 l2 = __float2bfloat16(az - __bfloat162float(h2));
    __nv_bfloat16 l3 = __float2bfloat16(aw - __bfloat162float(h3));
    __nv_bfloat162 hp0; hp0.x = h0; hp0.y = h1;
    __nv_bfloat162 hp1; hp1.x = h2; hp1.y = h3;
    __nv_bfloat162 lp0; lp0.x = l0; lp0.y = l1;
    __nv_bfloat162 lp1; lp1.x = l2; lp1.y = l3;
    uint2 hw, lw;
    hw.x = *(uint32_t*)&hp0; hw.y = *(uint32_t*)&hp1;
    lw.x = *(uint32_t*)&lp0; lw.y = *(uint32_t*)&lp1;
    const size_t o = ((size_t)n * E_ + e) >> 2;
    ((uint2*)Uh)[o] = hw;
    ((uint2*)Ul)[o] = lw;
}

// ---------------------------------------------------------------------------
extern "C" void kernel_launch(void* const* d_in, const int* in_sizes, int n_in,
                              void* d_out, int out_size)
{
    (void)in_sizes; (void)n_in; (void)out_size;
    const float* x     = (const float*)d_in[0];
    const float* W_in  = (const float*)d_in[1];
    const float* W_out = (const float*)d_in[2];
    float* out = (float*)d_out;

    __nv_bfloat16 *Xh, *Xl, *Wih, *Wil, *Woh, *Wol, *Uh, *Ul;
    float* Vf;
    cudaGetSymbolAddress((void**)&Xh, g_Xh);
    cudaGetSymbolAddress((void**)&Xl, g_Xl);
    cudaGetSymbolAddress((void**)&Wih, g_Wih);
    cudaGetSymbolAddress((void**)&Wil, g_Wil);
    cudaGetSymbolAddress((void**)&Woh, g_Woh);
    cudaGetSymbolAddress((void**)&Wol, g_Wol);
    cudaGetSymbolAddress((void**)&Vf, g_Vf);
    cudaGetSymbolAddress((void**)&Uh, g_Uh);
    cudaGetSymbolAddress((void**)&Ul, g_Ul);

    cudaFuncSetAttribute(gemm_mma, cudaFuncAttributeMaxDynamicSharedMemorySize, SM_TOTAL);

    // Split conversions
    conv_split<<<(M_ * E_ / 4 + 255) / 256, 256>>>(x, Xh, Xl, M_ * E_ / 4);
    conv_split<<<(E_ * E_ / 4 + 255) / 256, 256>>>(W_in, Wih, Wil, E_ * E_ / 4);
    conv_split<<<(E_ * E_ / 4 + 255) / 256, 256>>>(W_out, Woh, Wol, E_ * E_ / 4);

    dim3 gridGemm(E_ / GBN, M_ / GBM);   // (8, 128)
    // V = X @ W_in^T   (fp32 out for smoothing)
    gemm_mma<<<gridGemm, 256, SM_TOTAL>>>(Xh, Xl, Wih, Wil, Vf);
    // U = gaussian smooth of V (bf16 hi/lo out)
    smooth_kernel<<<M_, 256>>>(Vf, Uh, Ul);
    // out = U @ W_out^T (fp32 out)
    gemm_mma<<<gridGemm, 256, SM_TOTAL>>>(Uh, Ul, Woh, Wol, out);
}

// round 5
// speedup vs baseline: 3.2474x; 1.3084x over previous
#include <cuda_runtime.h>
#include <cuda_bf16.h>
#include <cstdint>

// Problem dims (fixed)
#define B_   8
#define L_   2048
#define E_   1024
#define M_   (B_ * L_)   // 16384
#define RAD  8

// ---------------------------------------------------------------------------
// Scratch (__device__ globals; allocation-free rule)
// ---------------------------------------------------------------------------
__device__ __nv_bfloat16 g_Xh[(size_t)M_ * E_];
__device__ __nv_bfloat16 g_Xl[(size_t)M_ * E_];
__device__ __nv_bfloat16 g_Wih[(size_t)E_ * E_];
__device__ __nv_bfloat16 g_Wil[(size_t)E_ * E_];
__device__ __nv_bfloat16 g_Woh[(size_t)E_ * E_];
__device__ __nv_bfloat16 g_Wol[(size_t)E_ * E_];
__device__ float         g_Vf [(size_t)M_ * E_];
__device__ __nv_bfloat16 g_Uh[(size_t)M_ * E_];
__device__ __nv_bfloat16 g_Ul[(size_t)M_ * E_];

__device__ __forceinline__ uint32_t smem_u32(const void* p) {
    uint32_t a;
    asm("{ .reg .u64 t; cvta.to.shared.u64 t, %1; cvt.u32.u64 %0, t; }" : "=r"(a) : "l"(p));
    return a;
}

#define CP_ASYNC16(dst, src) \
    asm volatile("cp.async.cg.shared.global [%0], [%1], 16;" :: "r"(dst), "l"(src))
#define CP_COMMIT() asm volatile("cp.async.commit_group;")
#define CP_WAIT(n)  asm volatile("cp.async.wait_group %0;" :: "n"(n))

// ---------------------------------------------------------------------------
// GEMM: C[M,1024] = A[M,1024] @ W[1024,1024]^T via bf16 split (3 HMMA terms),
// cp.async 3-stage pipelined. BM=BN=128, BK=64, 256 thr, warp tile 32x64.
// smem rows of 128B with SW128 swizzle -> conflict-free ldmatrix & stores.
// 3 stages x 64KB = 192KB -> 1 CTA/SM.
// ---------------------------------------------------------------------------
#define GBM 128
#define GBN 128
#define GBK 64
#define NCHUNK (E_ / GBK)   // 16

#define STG_BYTES 65536
#define T_AH 0
#define T_AL 16384
#define T_WH 32768
#define T_WL 49152
#define SM_TOTAL (3 * STG_BYTES)   // 196608

__global__ __launch_bounds__(256, 1) void gemm_mma(
    const __nv_bfloat16* __restrict__ Ah, const __nv_bfloat16* __restrict__ Al,
    const __nv_bfloat16* __restrict__ Wh, const __nv_bfloat16* __restrict__ Wl,
    float* __restrict__ C)
{
    extern __shared__ char smem[];
    const uint32_t smem_base = smem_u32(smem);

    const int tid  = threadIdx.x;
    const int wid  = tid >> 5;
    const int lane = tid & 31;
    const int wm   = wid & 3;    // M offset wm*32
    const int wn   = wid >> 2;   // N offset wn*64

    const size_t mrow0 = (size_t)blockIdx.y * GBM;
    const size_t nrow0 = (size_t)blockIdx.x * GBN;

    // cp.async source/dest addressing (4 reps of 256 threads -> 1024 16B ops/tile)
    uint32_t soff[4];
    size_t   gaoff[4], gwoff[4];
#pragma unroll
    for (int rep = 0; rep < 4; rep++) {
        const int u = tid + rep * 256;
        const int row = u >> 3, seg = u & 7;
        soff[rep] = (uint32_t)row * 128 + (uint32_t)((seg * 16) ^ ((row & 7) * 16));
        gaoff[rep] = (mrow0 + row) * E_ + seg * 8;
        gwoff[rep] = (nrow0 + row) * E_ + seg * 8;
    }

    // ldmatrix lane addressing (within one 128x64-bf16 tile)
    uint32_t aRow[2], bRow[4];
#pragma unroll
    for (int mt = 0; mt < 2; mt++)
        aRow[mt] = (uint32_t)(wm * 32 + mt * 16 + (lane & 15)) * 128;
#pragma unroll
    for (int g = 0; g < 4; g++)
        bRow[g] = (uint32_t)(wn * 64 + g * 16 + (lane & 7) + ((lane >> 4) & 1) * 8) * 128;
    const uint32_t cA = ((((lane >> 4) & 1) * 16) ^ ((lane & 7) * 16));
    const uint32_t cB = ((((lane >> 3) & 1) * 16) ^ ((lane & 7) * 16));

    float acc[2][8][4];
#pragma unroll
    for (int mt = 0; mt < 2; mt++)
#pragma unroll
        for (int nt = 0; nt < 8; nt++)
#pragma unroll
            for (int r = 0; r < 4; r++) acc[mt][nt][r] = 0.0f;

    // async load of one chunk into one stage
    auto load_chunk = [&](int ch, int stg) {
        const uint32_t sb = smem_base + (uint32_t)stg * STG_BYTES;
        const int kbase = ch * GBK;
#pragma unroll
        for (int rep = 0; rep < 4; rep++) {
            const uint32_t so = sb + soff[rep];
            CP_ASYNC16(so + T_AH, Ah + gaoff[rep] + kbase);
            CP_ASYNC16(so + T_AL, Al + gaoff[rep] + kbase);
            CP_ASYNC16(so + T_WH, Wh + gwoff[rep] + kbase);
            CP_ASYNC16(so + T_WL, Wl + gwoff[rep] + kbase);
        }
        CP_COMMIT();
    };

    load_chunk(0, 0);
    load_chunk(1, 1);

#pragma unroll 1
    for (int ch = 0; ch < NCHUNK; ch++) {
        if (ch + 1 < NCHUNK) { CP_WAIT(1); } else { CP_WAIT(0); }
        __syncthreads();
        if (ch + 2 < NCHUNK) load_chunk(ch + 2, (ch + 2) % 3);

        const uint32_t sb = smem_base + (uint32_t)(ch % 3) * STG_BYTES;
#pragma unroll
        for (int term = 0; term < 3; term++) {
            const uint32_t baseA = sb + (term == 2 ? T_AL : T_AH);
            const uint32_t baseW = sb + (term == 1 ? T_WL : T_WH);
#pragma unroll
            for (int ks = 0; ks < 4; ks++) {
                const uint32_t kb = (uint32_t)(ks * 32);
                uint32_t a[2][4];
#pragma unroll
                for (int mt = 0; mt < 2; mt++) {
                    const uint32_t ad = baseA + aRow[mt] + (kb ^ cA);
                    asm volatile(
                        "ldmatrix.sync.aligned.m8n8.x4.shared.b16 {%0,%1,%2,%3}, [%4];"
                        : "=r"(a[mt][0]), "=r"(a[mt][1]), "=r"(a[mt][2]), "=r"(a[mt][3])
                        : "r"(ad));
                }
                uint32_t b[8][2];
#pragma unroll
                for (int g = 0; g < 4; g++) {
                    const uint32_t bd = baseW + bRow[g] + (kb ^ cB);
                    uint32_t r0, r1, r2, r3;
                    asm volatile(
                        "ldmatrix.sync.aligned.m8n8.x4.shared.b16 {%0,%1,%2,%3}, [%4];"
                        : "=r"(r0), "=r"(r1), "=r"(r2), "=r"(r3)
                        : "r"(bd));
                    b[g * 2 + 0][0] = r0; b[g * 2 + 0][1] = r1;
                    b[g * 2 + 1][0] = r2; b[g * 2 + 1][1] = r3;
                }
#pragma unroll
                for (int mt = 0; mt < 2; mt++)
#pragma unroll
                    for (int nt = 0; nt < 8; nt++) {
                        asm volatile(
                            "mma.sync.aligned.m16n8k16.row.col.f32.bf16.bf16.f32 "
                            "{%0,%1,%2,%3}, {%4,%5,%6,%7}, {%8,%9}, {%0,%1,%2,%3};"
                            : "+f"(acc[mt][nt][0]), "+f"(acc[mt][nt][1]),
                              "+f"(acc[mt][nt][2]), "+f"(acc[mt][nt][3])
                            : "r"(a[mt][0]), "r"(a[mt][1]), "r"(a[mt][2]), "r"(a[mt][3]),
                              "r"(b[nt][0]), "r"(b[nt][1]));
                    }
            }
        }
    }

    // Epilogue: direct fp32 stores.
    const int qr = lane >> 2;
    const int qc = (lane & 3) * 2;
#pragma unroll
    for (int mt = 0; mt < 2; mt++) {
        const size_t r0 = mrow0 + wm * 32 + mt * 16 + qr;
#pragma unroll
        for (int nt = 0; nt < 8; nt++) {
            const size_t col = nrow0 + wn * 64 + nt * 8 + qc;
            *(float2*)(C + r0 * E_ + col)       = make_float2(acc[mt][nt][0], acc[mt][nt][1]);
            *(float2*)(C + (r0 + 8) * E_ + col) = make_float2(acc[mt][nt][2], acc[mt][nt][3]);
        }
    }
}

// ---------------------------------------------------------------------------
// fp32 -> bf16 hi/lo split conversion (float4 vectorized)
// ---------------------------------------------------------------------------
__global__ __launch_bounds__(256) void conv_split(
    const float* __restrict__ in, __nv_bfloat16* __restrict__ hi,
    __nv_bfloat16* __restrict__ lo, int n4)
{
    int idx = blockIdx.x * 256 + threadIdx.x;
    if (idx >= n4) return;
    float4 v = ((const float4*)in)[idx];
    __nv_bfloat16 h0 = __float2bfloat16(v.x), h1 = __float2bfloat16(v.y);
    __nv_bfloat16 h2 = __float2bfloat16(v.z), h3 = __float2bfloat16(v.w);
    __nv_bfloat16 l0 = __float2bfloat16(v.x - __bfloat162float(h0));
    __nv_bfloat16 l1 = __float2bfloat16(v.y - __bfloat162float(h1));
    __nv_bfloat16 l2 = __float2bfloat16(v.z - __bfloat162float(h2));
    __nv_bfloat16 l3 = __float2bfloat16(v.w - __bfloat162float(h3));
    __nv_bfloat162 hp0; hp0.x = h0; hp0.y = h1;
    __nv_bfloat162 hp1; hp1.x = h2; hp1.y = h3;
    __nv_bfloat162 lp0; lp0.x = l0; lp0.y = l1;
    __nv_bfloat162 lp1; lp1.x = l2; lp1.y = l3;
    uint2 hw, lw;
    hw.x = *(uint32_t*)&hp0; hw.y = *(uint32_t*)&hp1;
    lw.x = *(uint32_t*)&lp0; lw.y = *(uint32_t*)&lp1;
    ((uint2*)hi)[idx] = hw;
    ((uint2*)lo)[idx] = lw;
}

// ---------------------------------------------------------------------------
// Gaussian smoothing along sequence (17 taps, float4 over embed dim),
// reading fp32 V, writing bf16 hi/lo U for GEMM2.
// ---------------------------------------------------------------------------
__global__ __launch_bounds__(256) void smooth_kernel(
    const float* __restrict__ V, __nv_bfloat16* __restrict__ Uh,
    __nv_bfloat16* __restrict__ Ul)
{
    const float wt[RAD + 1] = {1.0f, 0.60653066f, 0.13533528f, 0.011108997f,
                               3.3546263e-4f, 3.7266532e-6f, 1.5229979e-8f,
                               2.2897348e-11f, 1.2664166e-14f};
    const int n = blockIdx.x;        // b*L + q
    const int b = n >> 11;
    const int q = n & (L_ - 1);
    const int e = threadIdx.x * 4;   // 4 consecutive embed cols
    const int h = e >> 7;            // head

    int c;
    switch (h) {
        case 0: case 5: c = q;      break;   // center
        case 1: case 6: c = q - 1;  break;   // left
        case 2: case 7: c = q + 1;  break;   // right
        case 3:         c = 0;      break;   // first
        default:        c = L_ - 1; break;   // last
    }

    float ax = 0.f, ay = 0.f, az = 0.f, aw = 0.f, wsum = 0.f;
#pragma unroll
    for (int d = -RAD; d <= RAD; d++) {
        const int j = c + d;
        if (j >= 0 && j < L_) {
            const float w = wt[d < 0 ? -d : d];
            wsum += w;
            const float4 v = *(const float4*)(V + ((size_t)b * L_ + j) * E_ + e);
            ax = fmaf(w, v.x, ax); ay = fmaf(w, v.y, ay);
            az = fmaf(w, v.z, az); aw = fmaf(w, v.w, aw);
        }
    }
    const float inv = 1.0f / wsum;
    ax *= inv; ay *= inv; az *= inv; aw *= inv;

    __nv_bfloat16 h0 = __float2bfloat16(ax), h1 = __float2bfloat16(ay);
    __nv_bfloat16 h2 = __float2bfloat16(az), h3 = __float2bfloat16(aw);
    __nv_bfloat16 l0 = __float2bfloat16(ax - __bfloat162float(h0));
    __nv_bfloat16 l1 = __float2bfloat16(ay - __bfloat162float(h1));
    __nv_bfloat16 l2 = __float2bfloat16(az - __bfloat162float(h2));
    __nv_bfloat16 l3 = __float2bfloat16(aw - __bfloat162float(h3));
    __nv_bfloat162 hp0; hp0.x = h0; hp0.y = h1;
    __nv_bfloat162 hp1; hp1.x = h2; hp1.y = h3;
    __nv_bfloat162 lp0; lp0.x = l0; lp0.y = l1;
    __nv_bfloat162 lp1; lp1.x = l2; lp1.y = l3;
    uint2 hw, lw;
    hw.x = *(uint32_t*)&hp0; hw.y = *(uint32_t*)&hp1;
    lw.x = *(uint32_t*)&lp0; lw.y = *(uint32_t*)&lp1;
    const size_t o = ((size_t)n * E_ + e) >> 2;
    ((uint2*)Uh)[o] = hw;
    ((uint2*)Ul)[o] = lw;
}

// ---------------------------------------------------------------------------
extern "C" void kernel_launch(void* const* d_in, const int* in_sizes, int n_in,
                              void* d_out, int out_size)
{
    (void)in_sizes; (void)n_in; (void)out_size;
    const float* x     = (const float*)d_in[0];
    const float* W_in  = (const float*)d_in[1];
    const float* W_out = (const float*)d_in[2];
    float* out = (float*)d_out;

    __nv_bfloat16 *Xh, *Xl, *Wih, *Wil, *Woh, *Wol, *Uh, *Ul;
    float* Vf;
    cudaGetSymbolAddress((void**)&Xh, g_Xh);
    cudaGetSymbolAddress((void**)&Xl, g_Xl);
    cudaGetSymbolAddress((void**)&Wih, g_Wih);
    cudaGetSymbolAddress((void**)&Wil, g_Wil);
    cudaGetSymbolAddress((void**)&Woh, g_Woh);
    cudaGetSymbolAddress((void**)&Wol, g_Wol);
    cudaGetSymbolAddress((void**)&Vf, g_Vf);
    cudaGetSymbolAddress((void**)&Uh, g_Uh);
    cudaGetSymbolAddress((void**)&Ul, g_Ul);

    cudaFuncSetAttribute(gemm_mma, cudaFuncAttributeMaxDynamicSharedMemorySize, SM_TOTAL);

    // Split conversions
    conv_split<<<(M_ * E_ / 4 + 255) / 256, 256>>>(x, Xh, Xl, M_ * E_ / 4);
    conv_split<<<(E_ * E_ / 4 + 255) / 256, 256>>>(W_in, Wih, Wil, E_ * E_ / 4);
    conv_split<<<(E_ * E_ / 4 + 255) / 256, 256>>>(W_out, Woh, Wol, E_ * E_ / 4);

    dim3 gridGemm(E_ / GBN, M_ / GBM);   // (8, 128)
    // V = X @ W_in^T   (fp32 out for smoothing)
    gemm_mma<<<gridGemm, 256, SM_TOTAL>>>(Xh, Xl, Wih, Wil, Vf);
    // U = gaussian smooth of V (bf16 hi/lo out)
    smooth_kernel<<<M_, 256>>>(Vf, Uh, Ul);
    // out = U @ W_out^T (fp32 out)
    gemm_mma<<<gridGemm, 256, SM_TOTAL>>>(Uh, Ul, Woh, Wol, out);
}